// round 2
// baseline (speedup 1.0000x reference)
#include <cuda_runtime.h>

#define NN   100000
#define NE   1000000
#define NG   2048
#define HID  64
#define ODIM 128

// Scratch (static __device__ globals — allocation-free per harness rules)
__device__ float d_dinv[NN];
__device__ float d_deg[NN];
__device__ float d_h[NN * HID];     // x @ W1
__device__ float d_agg1[NN * HID];  // layer-1 aggregation
__device__ float d_g[NN * HID];     // relu(h1) @ W2
__device__ float d_agg2[NN * HID];  // layer-2 aggregation
__device__ float d_pool[NG * HID];  // per-graph sums
__device__ float d_cnt[NG];         // per-graph node counts

__global__ void k_init() {
    int i = blockIdx.x * blockDim.x + threadIdx.x;
    if (i < NN * HID) { d_agg1[i] = 0.f; d_agg2[i] = 0.f; }
    if (i < NN)       d_deg[i] = 1.0f;   // self-loop contributes 1 to degree
    if (i < NG * HID) d_pool[i] = 0.f;
    if (i < NG)       d_cnt[i] = 0.f;
}

__global__ void k_deg(const int* __restrict__ dst) {
    int i = blockIdx.x * blockDim.x + threadIdx.x;
    if (i < NE) atomicAdd(&d_deg[dst[i]], 1.0f);
}

__global__ void k_dinv() {
    int i = blockIdx.x * blockDim.x + threadIdx.x;
    if (i < NN) d_dinv[i] = rsqrtf(d_deg[i]);
}

// h = x @ W1   (x: [NN,5], W1: [5,64]); 16 threads/node, float4 stores
__global__ void k_xw1(const float* __restrict__ x, const float* __restrict__ W1) {
    __shared__ float W1s[5 * HID];
    int tid = threadIdx.x;
    for (int i = tid; i < 5 * HID; i += blockDim.x) W1s[i] = W1[i];
    __syncthreads();
    int t = blockIdx.x * blockDim.x + tid;
    int n = t >> 4, c = t & 15;
    if (n >= NN) return;
    float xv[5];
#pragma unroll
    for (int k = 0; k < 5; k++) xv[k] = x[n * 5 + k];
    float o[4];
#pragma unroll
    for (int j = 0; j < 4; j++) {
        float s = 0.f;
#pragma unroll
        for (int k = 0; k < 5; k++) s += xv[k] * W1s[k * HID + c * 4 + j];
        o[j] = s;
    }
    *reinterpret_cast<float4*>(&d_h[(size_t)n * HID + c * 4]) =
        make_float4(o[0], o[1], o[2], o[3]);
}

// agg[dst] += h[src] * (dinv[src]*dinv[dst]); 16 threads/edge, float4 gather
__global__ void k_scatter(const int* __restrict__ src,
                          const int* __restrict__ dst,
                          const float* __restrict__ h,
                          float* __restrict__ agg) {
    int t = blockIdx.x * blockDim.x + threadIdx.x;
    int e = t >> 4, c = t & 15;
    if (e >= NE) return;
    int s = src[e], d = dst[e];
    float norm = d_dinv[s] * d_dinv[d];
    float4 v = *reinterpret_cast<const float4*>(&h[(size_t)s * HID + c * 4]);
    float* ap = &agg[(size_t)d * HID + c * 4];
    atomicAdd(ap + 0, v.x * norm);
    atomicAdd(ap + 1, v.y * norm);
    atomicAdd(ap + 2, v.z * norm);
    atomicAdd(ap + 3, v.w * norm);
}

// h1 = relu(agg1 + h*dinv^2 + b1);  g = h1 @ W2   (fused, 16 nodes/block)
__global__ void k_finish1(const float* __restrict__ b1, const float* __restrict__ W2) {
    __shared__ float W2s[HID * HID];
    __shared__ float h1s[16 * HID];
    __shared__ float b1s[HID];
    int tid = threadIdx.x;
    for (int i = tid; i < HID * HID; i += 256) W2s[i] = W2[i];
    if (tid < HID) b1s[tid] = b1[tid];
    __syncthreads();

    int nl = tid >> 4, c = tid & 15;
    int node = blockIdx.x * 16 + nl;
    if (node < NN) {
        float di = d_dinv[node];
        float sl = di * di;
#pragma unroll
        for (int j = 0; j < 4; j++) {
            int f = c * 4 + j;
            float v = d_agg1[(size_t)node * HID + f] + d_h[(size_t)node * HID + f] * sl + b1s[f];
            h1s[nl * HID + f] = fmaxf(v, 0.f);
        }
    } else {
#pragma unroll
        for (int j = 0; j < 4; j++) h1s[nl * HID + c * 4 + j] = 0.f;
    }
    __syncthreads();

    if (node < NN) {
        float acc[4] = {0.f, 0.f, 0.f, 0.f};
#pragma unroll
        for (int k = 0; k < HID; k++) {
            float hv = h1s[nl * HID + k];
#pragma unroll
            for (int j = 0; j < 4; j++) acc[j] += hv * W2s[k * HID + c * 4 + j];
        }
        *reinterpret_cast<float4*>(&d_g[(size_t)node * HID + c * 4]) =
            make_float4(acc[0], acc[1], acc[2], acc[3]);
    }
}

// h2 = relu(agg2 + g*dinv^2 + b2);  pool[batch[n]] += h2;  cnt[batch[n]] += 1
__global__ void k_finish2(const float* __restrict__ b2, const int* __restrict__ batch) {
    int t = blockIdx.x * blockDim.x + threadIdx.x;
    int n = t >> 4, c = t & 15;
    if (n >= NN) return;
    float di = d_dinv[n];
    float sl = di * di;
    int g = batch[n];
#pragma unroll
    for (int j = 0; j < 4; j++) {
        int f = c * 4 + j;
        float v = fmaxf(d_agg2[(size_t)n * HID + f] + d_g[(size_t)n * HID + f] * sl + b2[f], 0.f);
        atomicAdd(&d_pool[g * HID + f], v);
    }
    if (c == 0) atomicAdd(&d_cnt[g], 1.0f);
}

// per-graph: pooled = pool/max(cnt,1); z = relu(pooled@W3+b3); out = z@W4+b4
__global__ void k_head(const float* __restrict__ W3, const float* __restrict__ b3,
                       const float* __restrict__ W4, const float* __restrict__ b4,
                       float* __restrict__ out) {
    __shared__ float p[HID];
    __shared__ float z[HID];
    int g = blockIdx.x, tid = threadIdx.x;
    if (tid < HID) {
        float cnt = fmaxf(d_cnt[g], 1.0f);
        p[tid] = d_pool[g * HID + tid] / cnt;
    }
    __syncthreads();
    if (tid < HID) {
        float s = b3[tid];
#pragma unroll
        for (int k = 0; k < HID; k++) s += p[k] * W3[k * HID + tid];
        z[tid] = fmaxf(s, 0.f);
    }
    __syncthreads();
    float s = b4[tid];
#pragma unroll
    for (int k = 0; k < HID; k++) s += z[k] * W4[k * ODIM + tid];
    out[g * ODIM + tid] = s;
}

extern "C" void kernel_launch(void* const* d_in, const int* in_sizes, int n_in,
                              void* d_out, int out_size) {
    const float* x     = (const float*)d_in[0];
    const int*   ei    = (const int*)d_in[1];
    const int*   batch = (const int*)d_in[2];
    const float* W1 = (const float*)d_in[3];
    const float* b1 = (const float*)d_in[4];
    const float* W2 = (const float*)d_in[5];
    const float* b2 = (const float*)d_in[6];
    const float* W3 = (const float*)d_in[7];
    const float* b3 = (const float*)d_in[8];
    const float* W4 = (const float*)d_in[9];
    const float* b4 = (const float*)d_in[10];
    float* out = (float*)d_out;

    const int* src = ei;        // edge_index[0, :]
    const int* dst = ei + NE;   // edge_index[1, :]

    // static device-global scratch addresses (resolved at module load; these
    // helper pointers are only for the two k_scatter variants)
    static float* hptr = nullptr, *a1 = nullptr, *gptr = nullptr, *a2 = nullptr;
    if (!hptr) {
        void* p;
        cudaGetSymbolAddress(&p, d_h);    hptr = (float*)p;
        cudaGetSymbolAddress(&p, d_agg1); a1   = (float*)p;
        cudaGetSymbolAddress(&p, d_g);    gptr = (float*)p;
        cudaGetSymbolAddress(&p, d_agg2); a2   = (float*)p;
    }

    k_init<<<(NN * HID + 255) / 256, 256>>>();
    k_deg<<<(NE + 255) / 256, 256>>>(dst);
    k_dinv<<<(NN + 255) / 256, 256>>>();
    k_xw1<<<(NN * 16 + 255) / 256, 256>>>(x, W1);
    k_scatter<<<(NE * 16 + 255) / 256, 256>>>(src, dst, hptr, a1);
    k_finish1<<<(NN + 15) / 16, 256>>>(b1, W2);
    k_scatter<<<(NE * 16 + 255) / 256, 256>>>(src, dst, gptr, a2);
    k_finish2<<<(NN * 16 + 255) / 256, 256>>>(b2, batch);
    k_head<<<NG, 128>>>(W3, b3, W4, b4, out);
}

// round 3
// speedup vs baseline: 1.6419x; 1.6419x over previous
#include <cuda_runtime.h>

#define NN   100000
#define NE   1000000
#define NG   2048
#define HID  64
#define ODIM 128

__device__ float d_dinv[NN];
__device__ float d_deg[NN];
__device__ float d_h[NN * HID];     // x @ W1
__device__ float d_agg1[NN * HID];  // layer-1 aggregation
__device__ float d_g[NN * HID];     // relu(h1) @ W2
__device__ float d_agg2[NN * HID];  // layer-2 aggregation
__device__ float d_pool[NG * HID];  // per-graph sums
__device__ float d_cnt[NG];         // per-graph node counts

__device__ __forceinline__ void red_v4(float* ap, float a, float b, float c, float d) {
    asm volatile("red.global.add.v4.f32 [%0], {%1, %2, %3, %4};"
                 :: "l"(ap), "f"(a), "f"(b), "f"(c), "f"(d) : "memory");
}

// zero agg1+agg2 (float4), init deg=1 (self-loop), zero pool/cnt
__global__ void k_init() {
    int i = blockIdx.x * blockDim.x + threadIdx.x;
    float4 z = make_float4(0.f, 0.f, 0.f, 0.f);
    if (i < NN * HID / 4) {
        reinterpret_cast<float4*>(d_agg1)[i] = z;
        reinterpret_cast<float4*>(d_agg2)[i] = z;
    }
    if (i < NN)           d_deg[i] = 1.0f;
    if (i < NG * HID / 4) reinterpret_cast<float4*>(d_pool)[i] = z;
    if (i < NG)           d_cnt[i] = 0.f;
}

__global__ void k_deg(const int* __restrict__ dst) {
    int i = blockIdx.x * blockDim.x + threadIdx.x;
    if (i < NE) atomicAdd(&d_deg[dst[i]], 1.0f);
}

__global__ void k_dinv() {
    int i = blockIdx.x * blockDim.x + threadIdx.x;
    if (i < NN) d_dinv[i] = rsqrtf(d_deg[i]);
}

// h = x @ W1   (x: [NN,5], W1: [5,64]); 16 threads/node, float4 stores
__global__ void k_xw1(const float* __restrict__ x, const float* __restrict__ W1) {
    __shared__ float W1s[5 * HID];
    int tid = threadIdx.x;
    for (int i = tid; i < 5 * HID; i += blockDim.x) W1s[i] = W1[i];
    __syncthreads();
    int t = blockIdx.x * blockDim.x + tid;
    int n = t >> 4, c = t & 15;
    if (n >= NN) return;
    float xv[5];
#pragma unroll
    for (int k = 0; k < 5; k++) xv[k] = x[n * 5 + k];
    float o[4];
#pragma unroll
    for (int j = 0; j < 4; j++) {
        float s = 0.f;
#pragma unroll
        for (int k = 0; k < 5; k++) s += xv[k] * W1s[k * HID + c * 4 + j];
        o[j] = s;
    }
    *reinterpret_cast<float4*>(&d_h[(size_t)n * HID + c * 4]) =
        make_float4(o[0], o[1], o[2], o[3]);
}

// agg[dst] += h[src] * (dinv[src]*dinv[dst]); 16 threads/edge,
// one red.global.add.v4.f32 per thread (4M reds/launch instead of 16M atomics)
__global__ void k_scatter(const int* __restrict__ src,
                          const int* __restrict__ dst,
                          const float* __restrict__ h,
                          float* __restrict__ agg) {
    int t = blockIdx.x * blockDim.x + threadIdx.x;
    int e = t >> 4, c = t & 15;
    if (e >= NE) return;
    int s = src[e], d = dst[e];
    float norm = d_dinv[s] * d_dinv[d];
    float4 v = *reinterpret_cast<const float4*>(&h[(size_t)s * HID + c * 4]);
    red_v4(&agg[(size_t)d * HID + c * 4],
           v.x * norm, v.y * norm, v.z * norm, v.w * norm);
}

// h1 = relu(agg1 + h*dinv^2 + b1);  g = h1 @ W2   (fused, 16 nodes/block)
__global__ void k_finish1(const float* __restrict__ b1, const float* __restrict__ W2) {
    __shared__ float W2s[HID * HID];
    __shared__ float h1s[16 * HID];
    __shared__ float b1s[HID];
    int tid = threadIdx.x;
    for (int i = tid; i < HID * HID; i += 256) W2s[i] = W2[i];
    if (tid < HID) b1s[tid] = b1[tid];
    __syncthreads();

    int nl = tid >> 4, c = tid & 15;
    int node = blockIdx.x * 16 + nl;
    if (node < NN) {
        float di = d_dinv[node];
        float sl = di * di;
#pragma unroll
        for (int j = 0; j < 4; j++) {
            int f = c * 4 + j;
            float v = d_agg1[(size_t)node * HID + f] + d_h[(size_t)node * HID + f] * sl + b1s[f];
            h1s[nl * HID + f] = fmaxf(v, 0.f);
        }
    } else {
#pragma unroll
        for (int j = 0; j < 4; j++) h1s[nl * HID + c * 4 + j] = 0.f;
    }
    __syncthreads();

    if (node < NN) {
        float acc[4] = {0.f, 0.f, 0.f, 0.f};
#pragma unroll
        for (int k = 0; k < HID; k++) {
            float hv = h1s[nl * HID + k];
#pragma unroll
            for (int j = 0; j < 4; j++) acc[j] += hv * W2s[k * HID + c * 4 + j];
        }
        *reinterpret_cast<float4*>(&d_g[(size_t)node * HID + c * 4]) =
            make_float4(acc[0], acc[1], acc[2], acc[3]);
    }
}

// h2 = relu(agg2 + g*dinv^2 + b2);  pool[batch[n]] += h2 (red.v4);  cnt += 1
__global__ void k_finish2(const float* __restrict__ b2, const int* __restrict__ batch) {
    int t = blockIdx.x * blockDim.x + threadIdx.x;
    int n = t >> 4, c = t & 15;
    if (n >= NN) return;
    float di = d_dinv[n];
    float sl = di * di;
    int g = batch[n];
    float o[4];
#pragma unroll
    for (int j = 0; j < 4; j++) {
        int f = c * 4 + j;
        o[j] = fmaxf(d_agg2[(size_t)n * HID + f] + d_g[(size_t)n * HID + f] * sl + b2[f], 0.f);
    }
    red_v4(&d_pool[g * HID + c * 4], o[0], o[1], o[2], o[3]);
    if (c == 0) atomicAdd(&d_cnt[g], 1.0f);
}

// per-graph: pooled = pool/max(cnt,1); z = relu(pooled@W3+b3); out = z@W4+b4
__global__ void k_head(const float* __restrict__ W3, const float* __restrict__ b3,
                       const float* __restrict__ W4, const float* __restrict__ b4,
                       float* __restrict__ out) {
    __shared__ float p[HID];
    __shared__ float z[HID];
    int g = blockIdx.x, tid = threadIdx.x;
    if (tid < HID) {
        float cnt = fmaxf(d_cnt[g], 1.0f);
        p[tid] = d_pool[g * HID + tid] / cnt;
    }
    __syncthreads();
    if (tid < HID) {
        float s = b3[tid];
#pragma unroll
        for (int k = 0; k < HID; k++) s += p[k] * W3[k * HID + tid];
        z[tid] = fmaxf(s, 0.f);
    }
    __syncthreads();
    float s = b4[tid];
#pragma unroll
    for (int k = 0; k < HID; k++) s += z[k] * W4[k * ODIM + tid];
    out[g * ODIM + tid] = s;
}

extern "C" void kernel_launch(void* const* d_in, const int* in_sizes, int n_in,
                              void* d_out, int out_size) {
    const float* x     = (const float*)d_in[0];
    const int*   ei    = (const int*)d_in[1];
    const int*   batch = (const int*)d_in[2];
    const float* W1 = (const float*)d_in[3];
    const float* b1 = (const float*)d_in[4];
    const float* W2 = (const float*)d_in[5];
    const float* b2 = (const float*)d_in[6];
    const float* W3 = (const float*)d_in[7];
    const float* b3 = (const float*)d_in[8];
    const float* W4 = (const float*)d_in[9];
    const float* b4 = (const float*)d_in[10];
    float* out = (float*)d_out;

    const int* src = ei;        // edge_index[0, :]
    const int* dst = ei + NE;   // edge_index[1, :]

    static float* hptr = nullptr, *a1 = nullptr, *gptr = nullptr, *a2 = nullptr;
    if (!hptr) {
        void* p;
        cudaGetSymbolAddress(&p, d_h);    hptr = (float*)p;
        cudaGetSymbolAddress(&p, d_agg1); a1   = (float*)p;
        cudaGetSymbolAddress(&p, d_g);    gptr = (float*)p;
        cudaGetSymbolAddress(&p, d_agg2); a2   = (float*)p;
    }

    k_init<<<(NN * HID / 4 + 255) / 256, 256>>>();
    k_deg<<<(NE + 255) / 256, 256>>>(dst);
    k_dinv<<<(NN + 255) / 256, 256>>>();
    k_xw1<<<(NN * 16 + 255) / 256, 256>>>(x, W1);
    k_scatter<<<(NE * 16 + 255) / 256, 256>>>(src, dst, hptr, a1);
    k_finish1<<<(NN + 15) / 16, 256>>>(b1, W2);
    k_scatter<<<(NE * 16 + 255) / 256, 256>>>(src, dst, gptr, a2);
    k_finish2<<<(NN * 16 + 255) / 256, 256>>>(b2, batch);
    k_head<<<NG, 128>>>(W3, b3, W4, b4, out);
}